// round 2
// baseline (speedup 1.0000x reference)
#include <cuda_runtime.h>
#include <cstdint>

#define NN 100000
#define EE 1600000
#define DD 64
#define HH 256
#define OO 64

// -------- scratch (no allocs allowed) --------
__device__ float g_agg[(size_t)NN * DD];   // 25.6 MB, L2-resident during scatter
__device__ int   g_idx64;                  // 1 if edge_index is int64, 0 if int32

// -------- helpers --------
__device__ __forceinline__ uint32_t f2tf_u(float x) {
    uint32_t u;
    asm("cvt.rna.tf32.f32 %0, %1;" : "=r"(u) : "f"(x));
    return u;
}
__device__ __forceinline__ float f2tf(float x) { return __uint_as_float(f2tf_u(x)); }

__device__ __forceinline__ void mma_tf32(float& d0, float& d1, float& d2, float& d3,
                                         uint32_t a0, uint32_t a1, uint32_t a2, uint32_t a3,
                                         uint32_t b0, uint32_t b1) {
    asm volatile(
        "mma.sync.aligned.m16n8k8.row.col.f32.tf32.tf32.f32 "
        "{%0,%1,%2,%3}, {%4,%5,%6,%7}, {%8,%9}, {%0,%1,%2,%3};"
        : "+f"(d0), "+f"(d1), "+f"(d2), "+f"(d3)
        : "r"(a0), "r"(a1), "r"(a2), "r"(a3), "r"(b0), "r"(b1));
}

// ============================================================
// Kernel 0: detect index dtype + zero agg
// If edge_index is int64 (row indices < 100000, nonnegative), every odd
// 32-bit word of the first 16 entries is zero. For int32 those words are
// random row indices — all-zero has probability ~(1/100000)^16.
// ============================================================
__global__ void zero_agg_kernel(const int* __restrict__ ei_words) {
    int t = blockIdx.x * blockDim.x + threadIdx.x;
    if (t == 0) {
        int acc = 0;
#pragma unroll
        for (int i = 1; i < 32; i += 2) acc |= ei_words[i];
        g_idx64 = (acc == 0) ? 1 : 0;
    }
    const int total = NN * DD / 4;
    float4 z = make_float4(0.f, 0.f, 0.f, 0.f);
    for (int i = t; i < total; i += gridDim.x * blockDim.x)
        reinterpret_cast<float4*>(g_agg)[i] = z;
}

// ============================================================
// Kernel 1: scatter-add edge_attr rows into g_agg (vectorized red)
// One thread per (edge, 16-byte chunk): E*16 threads, fully coalesced reads.
// ============================================================
__global__ void scatter_kernel(const float* __restrict__ ea,
                               const int* __restrict__ ei) {
    long long t = (long long)blockIdx.x * blockDim.x + threadIdx.x;
    if (t >= (long long)EE * 16) return;
    int e = (int)(t >> 4);
    int c = (int)(t & 15);
    int is64 = g_idx64;
    int row = is64 ? ei[2 * e] : ei[e];   // little-endian low word for int64
    if ((unsigned)row >= (unsigned)NN) return;   // never fault, even if misdetected
    float4 v = __ldg(reinterpret_cast<const float4*>(ea) + (size_t)e * 16 + c);
    float* dst = g_agg + (size_t)row * DD + c * 4;
    asm volatile("red.global.add.v4.f32 [%0], {%1,%2,%3,%4};"
                 :: "l"(dst), "f"(v.x), "f"(v.y), "f"(v.z), "f"(v.w)
                 : "memory");
}

// ============================================================
// Kernel 2: fused MLP  out = relu([x||agg] @ W1 + b1) @ W2 + b2
// TILE_M = 128 rows per CTA, 256 threads, tf32 mma.sync m16n8k8.
//
// smem column layout is "fragment permuted": within every 8-col block,
// logical col j is stored at p(j) = ((j&3)<<1) | (j>>2), so the A-fragment
// pair (k+t, k+t+4) is one contiguous lds.64 at physical (k + 2t).
// Row strides are = 8 (mod 32) -> conflict-free 64-bit lds per half-warp phase.
// ============================================================
#define TILE_M    128
#define AS_STRIDE 136          // 128 + 8
#define HS_STRIDE 264          // 256 + 8
#define W2_STRIDE 72           // 64 + 8   (8t+g distinct banks)
#define AS_FLOATS (256 * W2_STRIDE)     // 18432: max(128*136=17408, W2 region)
#define HS_FLOATS (TILE_M * HS_STRIDE)  // 33792
#define SMEM_FLOATS (AS_FLOATS + HS_FLOATS + HH + OO)  // 52544 -> 210176 B

__global__ void __launch_bounds__(256, 1)
mlp_kernel(const float* __restrict__ x,
           const float* __restrict__ W1g, const float* __restrict__ b1g,
           const float* __restrict__ W2g, const float* __restrict__ b2g,
           float* __restrict__ out) {
    extern __shared__ float smem[];
    float* A_s  = smem;                       // also reused as W2_s later
    float* W2_s = smem;
    float* h_s  = smem + AS_FLOATS;
    float* b1_s = smem + AS_FLOATS + HS_FLOATS;
    float* b2_s = b1_s + HH;

    const int tid  = threadIdx.x;
    const int warp = tid >> 5;
    const int lane = tid & 31;
    const int g    = lane >> 2;    // 0..7
    const int t4   = lane & 3;     // 0..3
    const int m_base = blockIdx.x * TILE_M;

    if (tid < HH) b1_s[tid] = b1g[tid];
    if (tid < OO) b2_s[tid] = b2g[tid];

    // ---- Phase 0: load A tile [128 x 128] = [x | agg], tf32-rounded, permuted ----
#pragma unroll
    for (int i = 0; i < 16; i++) {
        int idx = tid + i * 256;        // 0..4095  (128 rows x 32 float4)
        int r = idx >> 5;
        int q = idx & 31;               // float4 index along 128 logical cols
        int gr = m_base + r;
        float4 v;
        if (gr < NN) {
            if (q < 16) v = __ldg(reinterpret_cast<const float4*>(x) + (size_t)gr * 16 + q);
            else        v = *(reinterpret_cast<const float4*>(g_agg) + (size_t)gr * 16 + (q - 16));
        } else {
            v = make_float4(0.f, 0.f, 0.f, 0.f);
        }
        int c0  = q * 4;                // logical col base
        int blk = c0 >> 3;
        int bp  = (c0 & 4) ? 1 : 0;     // perm: j in {0..3} -> {0,2,4,6}; {4..7} -> {1,3,5,7}
        float* dst = A_s + r * AS_STRIDE + blk * 8;
        dst[bp + 0] = f2tf(v.x);
        dst[bp + 2] = f2tf(v.y);
        dst[bp + 4] = f2tf(v.z);
        dst[bp + 6] = f2tf(v.w);
    }
    __syncthreads();

    // perm positions for accumulator columns 2t and 2t+1
    const int p0 = (((2 * t4) & 3) << 1) | ((2 * t4) >> 2);
    const int p1 = (((2 * t4 + 1) & 3) << 1) | ((2 * t4 + 1) >> 2);

    // ---- Phase 1: GEMM1 h = relu(A @ W1 + b1), two 128-col halves ----
#pragma unroll
    for (int half = 0; half < 2; half++) {
        float acc[8][2][4];
#pragma unroll
        for (int mt = 0; mt < 8; mt++)
#pragma unroll
            for (int nt = 0; nt < 2; nt++)
#pragma unroll
                for (int i = 0; i < 4; i++) acc[mt][nt][i] = 0.f;

        const int n0 = half * 128 + warp * 16;  // this warp's 16 cols (2 n-tiles)
#pragma unroll
        for (int kk = 0; kk < 128; kk += 8) {
            const float* w1p = W1g + (size_t)(kk + t4) * HH + n0 + g;
            uint32_t b00 = f2tf_u(__ldg(w1p));
            uint32_t b01 = f2tf_u(__ldg(w1p + 4 * HH));
            uint32_t b10 = f2tf_u(__ldg(w1p + 8));
            uint32_t b11 = f2tf_u(__ldg(w1p + 4 * HH + 8));
#pragma unroll
            for (int mt = 0; mt < 8; mt++) {
                int r0 = mt * 16 + g;
                float2 a02 = *reinterpret_cast<const float2*>(A_s + r0 * AS_STRIDE + kk + 2 * t4);
                float2 a13 = *reinterpret_cast<const float2*>(A_s + (r0 + 8) * AS_STRIDE + kk + 2 * t4);
                uint32_t a0 = __float_as_uint(a02.x);
                uint32_t a1 = __float_as_uint(a13.x);
                uint32_t a2 = __float_as_uint(a02.y);
                uint32_t a3 = __float_as_uint(a13.y);
                mma_tf32(acc[mt][0][0], acc[mt][0][1], acc[mt][0][2], acc[mt][0][3],
                         a0, a1, a2, a3, b00, b01);
                mma_tf32(acc[mt][1][0], acc[mt][1][1], acc[mt][1][2], acc[mt][1][3],
                         a0, a1, a2, a3, b10, b11);
            }
        }
        // epilogue: bias + relu + tf32-round, store permuted into h_s
#pragma unroll
        for (int mt = 0; mt < 8; mt++) {
#pragma unroll
            for (int nt = 0; nt < 2; nt++) {
                int cbase = n0 + nt * 8;
                float bias0 = b1_s[cbase + 2 * t4];
                float bias1 = b1_s[cbase + 2 * t4 + 1];
                int r0 = mt * 16 + g;
                h_s[r0 * HS_STRIDE + cbase + p0]       = f2tf(fmaxf(acc[mt][nt][0] + bias0, 0.f));
                h_s[r0 * HS_STRIDE + cbase + p1]       = f2tf(fmaxf(acc[mt][nt][1] + bias1, 0.f));
                h_s[(r0 + 8) * HS_STRIDE + cbase + p0] = f2tf(fmaxf(acc[mt][nt][2] + bias0, 0.f));
                h_s[(r0 + 8) * HS_STRIDE + cbase + p1] = f2tf(fmaxf(acc[mt][nt][3] + bias1, 0.f));
            }
        }
    }
    __syncthreads();   // all warps done with A_s

    // ---- stage W2 [256 x 64] into freed A_s region (tf32-rounded) ----
#pragma unroll
    for (int i = 0; i < 16; i++) {
        int idx = tid + i * 256;        // 4096 float4 = 256 rows x 16
        int r = idx >> 4;
        int q = idx & 15;
        float4 v = __ldg(reinterpret_cast<const float4*>(W2g) + (size_t)r * 16 + q);
        float* dst = W2_s + r * W2_STRIDE + q * 4;
        dst[0] = f2tf(v.x); dst[1] = f2tf(v.y); dst[2] = f2tf(v.z); dst[3] = f2tf(v.w);
    }
    __syncthreads();

    // ---- Phase 2: GEMM2 out = h @ W2 + b2 ----
    const int mg = warp >> 1;   // 0..3 -> m-tiles {2mg, 2mg+1}
    const int ng = warp & 1;    // 0..1 -> n cols [ng*32, ng*32+32)
    float acc2[2][4][4];
#pragma unroll
    for (int mt = 0; mt < 2; mt++)
#pragma unroll
        for (int nt = 0; nt < 4; nt++)
#pragma unroll
            for (int i = 0; i < 4; i++) acc2[mt][nt][i] = 0.f;

#pragma unroll 8
    for (int kk = 0; kk < 256; kk += 8) {
        uint32_t bb[4][2];
#pragma unroll
        for (int nt = 0; nt < 4; nt++) {
            int n = ng * 32 + nt * 8 + g;
            bb[nt][0] = __float_as_uint(W2_s[(kk + t4) * W2_STRIDE + n]);
            bb[nt][1] = __float_as_uint(W2_s[(kk + t4 + 4) * W2_STRIDE + n]);
        }
#pragma unroll
        for (int mt = 0; mt < 2; mt++) {
            int r0 = (mg * 2 + mt) * 16 + g;
            float2 a02 = *reinterpret_cast<const float2*>(h_s + r0 * HS_STRIDE + kk + 2 * t4);
            float2 a13 = *reinterpret_cast<const float2*>(h_s + (r0 + 8) * HS_STRIDE + kk + 2 * t4);
            uint32_t a0 = __float_as_uint(a02.x);
            uint32_t a1 = __float_as_uint(a13.x);
            uint32_t a2 = __float_as_uint(a02.y);
            uint32_t a3 = __float_as_uint(a13.y);
#pragma unroll
            for (int nt = 0; nt < 4; nt++)
                mma_tf32(acc2[mt][nt][0], acc2[mt][nt][1], acc2[mt][nt][2], acc2[mt][nt][3],
                         a0, a1, a2, a3, bb[nt][0], bb[nt][1]);
        }
    }

    // epilogue: bias, store float2
#pragma unroll
    for (int mt = 0; mt < 2; mt++) {
#pragma unroll
        for (int nt = 0; nt < 4; nt++) {
            int col = ng * 32 + nt * 8 + 2 * t4;
            float bias0 = b2_s[col];
            float bias1 = b2_s[col + 1];
            int row = m_base + (mg * 2 + mt) * 16 + g;
            if (row < NN)
                *reinterpret_cast<float2*>(out + (size_t)row * OO + col) =
                    make_float2(acc2[mt][nt][0] + bias0, acc2[mt][nt][1] + bias1);
            if (row + 8 < NN)
                *reinterpret_cast<float2*>(out + (size_t)(row + 8) * OO + col) =
                    make_float2(acc2[mt][nt][2] + bias0, acc2[mt][nt][3] + bias1);
        }
    }
}

// ============================================================
extern "C" void kernel_launch(void* const* d_in, const int* in_sizes, int n_in,
                              void* d_out, int out_size) {
    const float* x   = (const float*)d_in[0];
    const int*   ei  = (const int*)d_in[1];   // int32 or int64 (auto-detected)
    const float* ea  = (const float*)d_in[2];
    // d_in[3] = u, d_in[4] = batch : unused
    const float* W1  = (const float*)d_in[5];
    const float* b1  = (const float*)d_in[6];
    const float* W2  = (const float*)d_in[7];
    const float* b2  = (const float*)d_in[8];
    float* out = (float*)d_out;

    zero_agg_kernel<<<2048, 256>>>(ei);

    int sblocks = (EE * 16) / 256;            // 100000, exact
    scatter_kernel<<<sblocks, 256>>>(ea, ei);

    size_t smem_bytes = SMEM_FLOATS * sizeof(float);   // 210176
    cudaFuncSetAttribute(mlp_kernel, cudaFuncAttributeMaxDynamicSharedMemorySize,
                         (int)smem_bytes);
    int mblocks = (NN + TILE_M - 1) / TILE_M;   // 782
    mlp_kernel<<<mblocks, 256, smem_bytes>>>(x, W1, b1, W2, b2, out);
}